// round 13
// baseline (speedup 1.0000x reference)
#include <cuda_runtime.h>
#include <cstdint>

#define Bq 16
#define Nq 2048
#define Cq 3
#define Kq 100
#define THREADS 1024
#define PER (Nq / THREADS)   // 2 sorted positions per thread (contiguous, base=2*tid)
#define NWORD (Nq / 64)      // 32 bitmap words
#define NTILE (Nq / 64)      // 32 tiles of 64 sorted positions
#define KCAP 112
#define NEGV (-1e9f)
#define HSTRIDE 66           // u16 histogram row stride (bank-conflict-free scan)

// dynamic smem layout (bytes)
#define OFF_KEYSA 0
#define OFF_KEYSB 16384
#define OFF_LOHI  32768
#define OFF_HIST  49152                       // u16[256*66] = 33792
#define OFF_DTOT  (49152 + 33792)             // u32[256]
#define OFF_DBASE (OFF_DTOT + 1024)           // u32[256]
#define SMEM_DYN  (OFF_DBASE + 1024)          // 84992

typedef unsigned long long u64;

__device__ __forceinline__ unsigned fkey_desc(float f) {
    unsigned u = __float_as_uint(f);
    u = (u & 0x80000000u) ? ~u : (u | 0x80000000u);
    return ~u;
}
__device__ __forceinline__ float key_to_score(unsigned k) {
    unsigned u = ~k;
    u = (u & 0x80000000u) ? (u & 0x7fffffffu) : ~u;
    return __uint_as_float(u);
}

// Exactly equivalent to (inter / fmaxf(uni,1e-8f)) > 0.5f for pairs that matter
// (alive boxes have width >= 10 so uni >= 10). Band fallback uses the literal
// reference expression; division rounding (<=0.5ulp) can't cross the band.
__device__ __forceinline__ bool iou_gt_half(float inter, float uni) {
    float h = 0.5f * uni;
    if (inter > h * 1.000002f) return true;
    if (inter < h * 0.999998f) return false;
    return inter / fmaxf(uni, 1e-8f) > 0.5f;
}

__device__ __forceinline__ bool supp_test(float lo, float hi, float wb, float2 p) {
    float inter = fminf(p.y, hi) - fmaxf(p.x, lo);
    float uni   = (p.y - p.x) + wb - inter;
    return (inter > 0.0f) && iou_gt_half(inter, uni);
}

__global__ void __launch_bounds__(THREADS)
roiheads_kernel(const float* __restrict__ logit,   // [B,N,3]
                const float* __restrict__ reg,     // [B,N,6]
                const float* __restrict__ prop,    // [B,N,2]
                const int*   __restrict__ ishape,  // scalar
                float*       __restrict__ out)     // [B,2,K,3]
{
    extern __shared__ unsigned char dynsm[];
    u64*            keysA = (u64*)(dynsm + OFF_KEYSA);
    u64*            keysB = (u64*)(dynsm + OFF_KEYSB);
    float2*         lohi  = (float2*)(dynsm + OFF_LOHI);
    unsigned short* hist  = (unsigned short*)(dynsm + OFF_HIST);
    unsigned*       dtot  = (unsigned*)(dynsm + OFF_DTOT);
    unsigned*       dbase = (unsigned*)(dynsm + OFF_DBASE);

    __shared__ float2 keptLH[KCAP];
    __shared__ u64    alive[NWORD];
    __shared__ int    sStopT;
    __shared__ int    wp[NWORD + 1];

    const int b    = blockIdx.x >> 1;
    const int c    = blockIdx.x & 1;
    const int cls  = c + 1;
    const int tid  = threadIdx.x;
    const int lane = tid & 31;
    const int wid  = tid >> 5;
    const int base = tid * PER;

    int ib = ishape[0];
    float img = (ib > 0 && ib < (1 << 24)) ? (float)ib : __int_as_float(ib);

    if (tid < NWORD) alive[tid] = 0ull;
    if (tid == 0) sStopT = NTILE - 1;

    // ---------- Phase 1: softmax + decode + clip + mask -> keysA ----------
    {
        const float2* lgv = (const float2*)(logit + ((size_t)b * Nq + base) * Cq);
        float2 G0 = lgv[0], G1 = lgv[1], G2 = lgv[2];
        const float4  P   = *(const float4*)(prop + ((size_t)b * Nq + base) * 2);
        float lg[6] = {G0.x, G0.y, G1.x, G1.y, G2.x, G2.y};
        float pr[4] = {P.x, P.y, P.z, P.w};

        #pragma unroll
        for (int r = 0; r < PER; r++) {
            int j = base + r;
            float l0 = lg[r*3+0], l1 = lg[r*3+1], l2 = lg[r*3+2];
            float m  = fmaxf(l0, fmaxf(l1, l2));
            float e0 = expf(l0 - m), e1 = expf(l1 - m), e2 = expf(l2 - m);
            float s  = ((cls == 1) ? e1 : e2) / (e0 + e1 + e2);

            const float2 dd = *(const float2*)(reg + ((size_t)b * Nq + j) * (2 * Cq) + 2 * cls);
            float dx = dd.x;
            float dw = fminf(dd.y, 4.0f);

            float p0 = pr[r*2+0], p1 = pr[r*2+1];
            float w   = p1 - p0;
            float ctr = p0 + 0.5f * w;
            float pc  = dx * w + ctr;
            float pw  = expf(dw) * w;
            float lo  = fminf(fmaxf(pc - 0.5f * pw, 0.0f), img);
            float hi  = fminf(fmaxf(pc + 0.5f * pw, 0.0f), img);

            bool  valid = ((hi - lo) >= 10.0f) && (s >= 0.05f);
            float ms    = valid ? s : NEGV;

            lohi[j]  = make_float2(lo, hi);
            keysA[j] = ((u64)fkey_desc(ms) << 32) | (unsigned)j;
        }
    }
    __syncthreads();

    // ---------- Phase 2: stable LSD radix sort on score key (4 x 8-bit) ----------
    {
        u64* src = keysA;
        u64* dst = keysB;
        const unsigned lt = (1u << lane) - 1u;
        #pragma unroll
        for (int p = 0; p < 4; p++) {
            const int sh = 32 + p * 8;
            for (int i = tid; i < 256 * HSTRIDE; i += THREADS) hist[i] = 0;
            __syncthreads();

            u64 k0 = src[tid];
            u64 k1 = src[tid + 1024];
            unsigned d0 = (unsigned)(k0 >> sh) & 0xFFu;
            unsigned d1 = (unsigned)(k1 >> sh) & 0xFFu;
            unsigned m0 = __match_any_sync(0xffffffffu, d0);
            unsigned m1 = __match_any_sync(0xffffffffu, d1);
            if (__ffs(m0) - 1 == lane)
                hist[d0 * HSTRIDE + wid]      = (unsigned short)__popc(m0);
            if (__ffs(m1) - 1 == lane)
                hist[d1 * HSTRIDE + 32 + wid] = (unsigned short)__popc(m1);
            __syncthreads();

            if (tid < 256) {           // per-digit exclusive row prefix (in place)
                unsigned short* h = hist + tid * HSTRIDE;
                unsigned sum = 0;
                #pragma unroll
                for (int i = 0; i < 64; i++) {
                    unsigned t = h[i];
                    h[i] = (unsigned short)sum;
                    sum += t;
                }
                dtot[tid] = sum;
            }
            __syncthreads();

            if (tid < 32) {            // exclusive scan of 256 digit totals
                unsigned t8[8], run = 0;
                #pragma unroll
                for (int i = 0; i < 8; i++) t8[i] = dtot[tid * 8 + i];
                #pragma unroll
                for (int i = 0; i < 8; i++) { unsigned u = t8[i]; t8[i] = run; run += u; }
                unsigned inc = run;
                #pragma unroll
                for (int d = 1; d < 32; d <<= 1) {
                    unsigned x = __shfl_up_sync(0xffffffffu, inc, d);
                    if (lane >= d) inc += x;
                }
                unsigned excl = inc - run;
                #pragma unroll
                for (int i = 0; i < 8; i++) dbase[tid * 8 + i] = excl + t8[i];
            }
            __syncthreads();

            dst[dbase[d0] + hist[d0 * HSTRIDE + wid]      + __popc(m0 & lt)] = k0;
            dst[dbase[d1] + hist[d1 * HSTRIDE + 32 + wid] + __popc(m1 & lt)] = k1;
            __syncthreads();

            u64* tmp = src; src = dst; dst = tmp;   // after 4 passes: data in keysA
        }
    }

    // ---------- Phase 3: cache owned boxes; validity bitmap ----------
    u64 myKey[PER];
    float myLo[PER], myHi[PER];
    unsigned myAlive = 0;
    #pragma unroll
    for (int r = 0; r < PER; r++) {
        u64 key = keysA[base + r];
        myKey[r] = key;
        float2 lh = lohi[(int)(key & 0xffffffffu)];
        myLo[r] = lh.x;
        myHi[r] = lh.y;
        if (key_to_score((unsigned)(key >> 32)) > 0.5f * NEGV)
            myAlive |= (1u << r);
    }
    if (myAlive)
        atomicOr(&alive[wid], (u64)myAlive << (lane * PER));
    __syncthreads();

    // ---------- Phase 4: single-warp barrier-free greedy NMS sweep ----------
    if (wid == 0) {
        int kt = 0;
        int stopT = NTILE - 1;
        for (int t = 0; t < NTILE; t++) {
            u64 at = alive[t];               // validity mask (stable since barrier)
            if (at == 0ull) continue;        // nothing alive in this tile

            // load tile boxes: 2 per lane
            float2 a0 = lohi[(int)(keysA[t * 64 + lane     ] & 0xffffffffu)];
            float2 a1 = lohi[(int)(keysA[t * 64 + lane + 32] & 0xffffffffu)];
            const float glo0 = a0.x, ghi0 = a0.y, glo1 = a1.x, ghi1 = a1.y;
            const float w0 = ghi0 - glo0, w1 = ghi1 - glo1;

            // suppress vs full kept list so far (pipelined, unrolled x4)
            if (kt > 0) {
                bool q0 = false, q1 = false;
                int s = 0;
                for (; s + 4 <= kt; s += 4) {
                    float2 p0 = keptLH[s],   p1 = keptLH[s+1];
                    float2 p2 = keptLH[s+2], p3 = keptLH[s+3];
                    q0 |= supp_test(glo0, ghi0, w0, p0) | supp_test(glo0, ghi0, w0, p1)
                        | supp_test(glo0, ghi0, w0, p2) | supp_test(glo0, ghi0, w0, p3);
                    q1 |= supp_test(glo1, ghi1, w1, p0) | supp_test(glo1, ghi1, w1, p1)
                        | supp_test(glo1, ghi1, w1, p2) | supp_test(glo1, ghi1, w1, p3);
                }
                for (; s < kt; s++) {
                    float2 p = keptLH[s];
                    q0 |= supp_test(glo0, ghi0, w0, p);
                    q1 |= supp_test(glo1, ghi1, w1, p);
                }
                unsigned b0 = __ballot_sync(0xffffffffu, q0);
                unsigned b1 = __ballot_sync(0xffffffffu, q1);
                at &= ~(((u64)b1 << 32) | (u64)b0);
            }

            // greedy over the tile, capped at Kq kept total
            u64 kept = 0;
            while (at && kt < Kq) {
                int pos = __ffsll((long long)at) - 1;
                kept |= (1ull << pos);
                float candL = (pos & 32) ? glo1 : glo0;
                float candH = (pos & 32) ? ghi1 : ghi0;
                u64 packed = ((u64)__float_as_uint(candH) << 32) | __float_as_uint(candL);
                u64 got = __shfl_sync(0xffffffffu, packed, pos & 31);
                float pl = __uint_as_float((unsigned)(got & 0xffffffffu));
                float ph = __uint_as_float((unsigned)(got >> 32));
                float pw = ph - pl;
                bool q0 = false, q1 = false;
                {
                    float inter = fminf(ph, ghi0) - fmaxf(pl, glo0);
                    if (inter > 0.0f) q0 = iou_gt_half(inter, pw + w0 - inter);
                    inter = fminf(ph, ghi1) - fmaxf(pl, glo1);
                    if (inter > 0.0f) q1 = iou_gt_half(inter, pw + w1 - inter);
                }
                unsigned b0 = __ballot_sync(0xffffffffu, q0);
                unsigned b1 = __ballot_sync(0xffffffffu, q1);
                at &= ~(((u64)b1 << 32) | (u64)b0);
                at = (pos < 63) ? (at & (~0ull << (pos + 1))) : 0ull;
                if (lane == 0) keptLH[kt] = make_float2(pl, ph);
                kt++;
            }
            if (lane == 0) alive[t] = kept;   // plain store; read after barrier
            if (kt >= Kq) { stopT = t; break; }
        }
        if (lane == 0) sStopT = stopT;
    }
    __syncthreads();

    if (tid < NWORD && tid > sStopT) alive[tid] = 0ull;
    __syncthreads();

    // ---------- Phase 5: ranks + emit top-K with NEG padding ----------
    if (tid == 0) {
        int acc = 0;
        #pragma unroll
        for (int w = 0; w < NWORD; w++) { wp[w] = acc; acc += __popcll(alive[w]); }
        wp[NWORD] = acc;
    }
    __syncthreads();
    const int T = wp[NWORD];
    float* o = out + ((size_t)(b * 2 + c)) * Kq * 3;

    const u64 aw = alive[wid];
    #pragma unroll
    for (int r = 0; r < PER; r++) {
        int p = base + r;
        int bit = p & 63;
        u64 lowmask = (bit == 0) ? 0ull : ((1ull << bit) - 1ull);
        int  kr   = wp[p >> 6] + __popcll(aw & lowmask);
        bool kept = (aw >> bit) & 1ull;
        if (kept) {
            if (kr < Kq) {
                o[kr * 3 + 0] = myLo[r];
                o[kr * 3 + 1] = myHi[r];
                o[kr * 3 + 2] = key_to_score((unsigned)(myKey[r] >> 32));
            }
        } else {
            int nr = p - kr;
            if (T < Kq && nr < Kq - T) {
                int slot = T + nr;
                o[slot * 3 + 0] = myLo[r];
                o[slot * 3 + 1] = myHi[r];
                o[slot * 3 + 2] = NEGV;
            }
        }
    }
}

extern "C" void kernel_launch(void* const* d_in, const int* in_sizes, int n_in,
                              void* d_out, int out_size)
{
    const float* logit  = (const float*)d_in[0];   // [16,2048,3]
    const float* reg    = (const float*)d_in[1];   // [16,2048,6]
    const float* prop   = (const float*)d_in[2];   // [16,2048,2]
    const int*   ishape = (const int*)d_in[3];     // scalar
    float* out = (float*)d_out;                    // [16,2,100,3]

    cudaFuncSetAttribute(roiheads_kernel,
                         cudaFuncAttributeMaxDynamicSharedMemorySize, SMEM_DYN);
    roiheads_kernel<<<Bq * (Cq - 1), THREADS, SMEM_DYN>>>(logit, reg, prop, ishape, out);
}

// round 14
// speedup vs baseline: 4.0443x; 4.0443x over previous
#include <cuda_runtime.h>
#include <cstdint>

#define Bq 16
#define Nq 2048
#define Cq 3
#define Kq 100
#define THREADS 1024
#define PER (Nq / THREADS)   // 2 sorted positions per thread (contiguous, base=2*tid)
#define NWORD (Nq / 64)      // 32 bitmap words
#define NTILE (Nq / 64)      // 32 tiles of 64 sorted positions
#define NPAIR (NTILE / 2)    // 16 paired rounds
#define KCAP 112
#define NEGV (-1e9f)
#define HSTRIDE 66           // u16 histogram row stride (bank-conflict-free scan)

// dynamic smem layout (bytes)
#define OFF_KEYSA 0
#define OFF_KEYSB 16384
#define OFF_LOHI  32768
#define OFF_HIST  49152                       // u16[256*66] = 33792
#define OFF_DTOT  (49152 + 33792)             // u32[256]
#define OFF_DBASE (OFF_DTOT + 1024)           // u32[256]
#define SMEM_DYN  (OFF_DBASE + 1024)          // 84992

typedef unsigned long long u64;

__device__ __forceinline__ unsigned fkey_desc(float f) {
    unsigned u = __float_as_uint(f);
    u = (u & 0x80000000u) ? ~u : (u | 0x80000000u);
    return ~u;
}
__device__ __forceinline__ float key_to_score(unsigned k) {
    unsigned u = ~k;
    u = (u & 0x80000000u) ? (u & 0x7fffffffu) : ~u;
    return __uint_as_float(u);
}

// Exactly equivalent to (inter / fmaxf(uni,1e-8f)) > 0.5f for pairs that matter
// (alive boxes have width >= 10 so uni >= 10). Band fallback uses the literal
// reference expression; division rounding (<=0.5ulp) can't cross the band.
__device__ __forceinline__ bool iou_gt_half(float inter, float uni) {
    float h = 0.5f * uni;
    if (inter > h * 1.000002f) return true;
    if (inter < h * 0.999998f) return false;
    return inter / fmaxf(uni, 1e-8f) > 0.5f;
}

__device__ __forceinline__ bool supp_test(float lo, float hi, float wb, float2 p) {
    float inter = fminf(p.y, hi) - fmaxf(p.x, lo);
    float uni   = (p.y - p.x) + wb - inter;
    return (inter > 0.0f) && iou_gt_half(inter, uni);
}

__global__ void __launch_bounds__(THREADS)
roiheads_kernel(const float* __restrict__ logit,   // [B,N,3]
                const float* __restrict__ reg,     // [B,N,6]
                const float* __restrict__ prop,    // [B,N,2]
                const int*   __restrict__ ishape,  // scalar
                float*       __restrict__ out)     // [B,2,K,3]
{
    extern __shared__ unsigned char dynsm[];
    u64*            keysA = (u64*)(dynsm + OFF_KEYSA);
    u64*            keysB = (u64*)(dynsm + OFF_KEYSB);
    float2*         lohi  = (float2*)(dynsm + OFF_LOHI);
    unsigned short* hist  = (unsigned short*)(dynsm + OFF_HIST);
    unsigned*       dtot  = (unsigned*)(dynsm + OFF_DTOT);
    unsigned*       dbase = (unsigned*)(dynsm + OFF_DBASE);

    __shared__ float2 keptLH[KCAP];
    __shared__ u64    alive[NWORD];
    __shared__ int    sDLo, sDHi;
    __shared__ int    sStop, sStopT;
    __shared__ int    wp[NWORD + 1];

    const int b    = blockIdx.x >> 1;
    const int c    = blockIdx.x & 1;
    const int cls  = c + 1;
    const int tid  = threadIdx.x;
    const int lane = tid & 31;
    const int wid  = tid >> 5;           // warp id == owned NMS tile
    const int base = tid * PER;

    int ib = ishape[0];
    float img = (ib > 0 && ib < (1 << 24)) ? (float)ib : __int_as_float(ib);

    if (tid < NWORD) alive[tid] = 0ull;
    if (tid == 0) { sDLo = 0; sDHi = 0; sStop = 0; sStopT = NTILE - 1; }

    // ---------- Phase 1: softmax + decode + clip + mask -> keysA ----------
    {
        const float2* lgv = (const float2*)(logit + ((size_t)b * Nq + base) * Cq);
        float2 G0 = lgv[0], G1 = lgv[1], G2 = lgv[2];
        const float4  P   = *(const float4*)(prop + ((size_t)b * Nq + base) * 2);
        float lg[6] = {G0.x, G0.y, G1.x, G1.y, G2.x, G2.y};
        float pr[4] = {P.x, P.y, P.z, P.w};

        #pragma unroll
        for (int r = 0; r < PER; r++) {
            int j = base + r;
            float l0 = lg[r*3+0], l1 = lg[r*3+1], l2 = lg[r*3+2];
            float m  = fmaxf(l0, fmaxf(l1, l2));
            float e0 = expf(l0 - m), e1 = expf(l1 - m), e2 = expf(l2 - m);
            float s  = ((cls == 1) ? e1 : e2) / (e0 + e1 + e2);

            const float2 dd = *(const float2*)(reg + ((size_t)b * Nq + j) * (2 * Cq) + 2 * cls);
            float dx = dd.x;
            float dw = fminf(dd.y, 4.0f);

            float p0 = pr[r*2+0], p1 = pr[r*2+1];
            float w   = p1 - p0;
            float ctr = p0 + 0.5f * w;
            float pc  = dx * w + ctr;
            float pw  = expf(dw) * w;
            float lo  = fminf(fmaxf(pc - 0.5f * pw, 0.0f), img);
            float hi  = fminf(fmaxf(pc + 0.5f * pw, 0.0f), img);

            bool  valid = ((hi - lo) >= 10.0f) && (s >= 0.05f);
            float ms    = valid ? s : NEGV;

            lohi[j]  = make_float2(lo, hi);
            keysA[j] = ((u64)fkey_desc(ms) << 32) | (unsigned)j;
        }
    }
    __syncthreads();

    // ---------- Phase 2: stable LSD radix sort on score key (4 x 8-bit) ----------
    {
        u64* src = keysA;
        u64* dst = keysB;
        const unsigned lt = (1u << lane) - 1u;
        #pragma unroll
        for (int p = 0; p < 4; p++) {
            const int sh = 32 + p * 8;
            for (int i = tid; i < 256 * HSTRIDE; i += THREADS) hist[i] = 0;
            __syncthreads();

            u64 k0 = src[tid];
            u64 k1 = src[tid + 1024];
            unsigned d0 = (unsigned)(k0 >> sh) & 0xFFu;
            unsigned d1 = (unsigned)(k1 >> sh) & 0xFFu;
            unsigned m0 = __match_any_sync(0xffffffffu, d0);
            unsigned m1 = __match_any_sync(0xffffffffu, d1);
            if (__ffs(m0) - 1 == lane)
                hist[d0 * HSTRIDE + wid]      = (unsigned short)__popc(m0);
            if (__ffs(m1) - 1 == lane)
                hist[d1 * HSTRIDE + 32 + wid] = (unsigned short)__popc(m1);
            __syncthreads();

            if (tid < 256) {           // per-digit exclusive row prefix (in place)
                unsigned short* h = hist + tid * HSTRIDE;
                unsigned sum = 0;
                #pragma unroll
                for (int i = 0; i < 64; i++) {
                    unsigned t = h[i];
                    h[i] = (unsigned short)sum;
                    sum += t;
                }
                dtot[tid] = sum;
            }
            __syncthreads();

            if (tid < 32) {            // exclusive scan of 256 digit totals
                unsigned t8[8], run = 0;
                #pragma unroll
                for (int i = 0; i < 8; i++) t8[i] = dtot[tid * 8 + i];
                #pragma unroll
                for (int i = 0; i < 8; i++) { unsigned u = t8[i]; t8[i] = run; run += u; }
                unsigned inc = run;
                #pragma unroll
                for (int d = 1; d < 32; d <<= 1) {
                    unsigned x = __shfl_up_sync(0xffffffffu, inc, d);
                    if (lane >= d) inc += x;
                }
                unsigned excl = inc - run;
                #pragma unroll
                for (int i = 0; i < 8; i++) dbase[tid * 8 + i] = excl + t8[i];
            }
            __syncthreads();

            dst[dbase[d0] + hist[d0 * HSTRIDE + wid]      + __popc(m0 & lt)] = k0;
            dst[dbase[d1] + hist[d1 * HSTRIDE + 32 + wid] + __popc(m1 & lt)] = k1;
            __syncthreads();

            u64* tmp = src; src = dst; dst = tmp;   // after 4 passes: data in keysA
        }
    }

    // ---------- Phase 3: cache owned boxes; validity bitmap ----------
    u64 myKey[PER];
    float myLo[PER], myHi[PER];
    unsigned myAlive = 0;
    #pragma unroll
    for (int r = 0; r < PER; r++) {
        u64 key = keysA[base + r];
        myKey[r] = key;
        float2 lh = lohi[(int)(key & 0xffffffffu)];
        myLo[r] = lh.x;
        myHi[r] = lh.y;
        if (key_to_score((unsigned)(key >> 32)) > 0.5f * NEGV)
            myAlive |= (1u << r);
    }
    if (myAlive)
        atomicOr(&alive[wid], (u64)myAlive << (lane * PER));
    __syncthreads();

    // ---------- Phase 4: paired-tile rounds (2 tiles / barrier) ----------
    int kt = 0;           // warp0 kept total (uniform in warp0)
    int dLo = 0, dHi = 0; // delta carried from previous ACTIVE round

    // warp0 helper: suppress tile vs keptLH[sLo,sHi), then greedy; updates kt.
    auto do_tile = [&](int t, u64 at, int sLo, int sHi) {
        float2 a0 = lohi[(int)(keysA[t * 64 + lane     ] & 0xffffffffu)];
        float2 a1 = lohi[(int)(keysA[t * 64 + lane + 32] & 0xffffffffu)];
        const float glo0 = a0.x, ghi0 = a0.y, glo1 = a1.x, ghi1 = a1.y;
        const float w0 = ghi0 - glo0, w1 = ghi1 - glo1;

        if (at != 0ull && sHi > sLo) {
            bool q0 = false, q1 = false;
            for (int s = sLo; s < sHi; s++) {
                float2 p = keptLH[s];
                q0 |= supp_test(glo0, ghi0, w0, p);
                q1 |= supp_test(glo1, ghi1, w1, p);
            }
            unsigned b0 = __ballot_sync(0xffffffffu, q0);
            unsigned b1 = __ballot_sync(0xffffffffu, q1);
            at &= ~(((u64)b1 << 32) | (u64)b0);
        }

        u64 kept = 0;
        while (at && kt < Kq) {
            int pos = __ffsll((long long)at) - 1;
            kept |= (1ull << pos);
            float candL = (pos & 32) ? glo1 : glo0;
            float candH = (pos & 32) ? ghi1 : ghi0;
            u64 packed = ((u64)__float_as_uint(candH) << 32) | __float_as_uint(candL);
            u64 got = __shfl_sync(0xffffffffu, packed, pos & 31);
            float pl = __uint_as_float((unsigned)(got & 0xffffffffu));
            float ph = __uint_as_float((unsigned)(got >> 32));
            float pw = ph - pl;
            bool q0 = false, q1 = false;
            {
                float inter = fminf(ph, ghi0) - fmaxf(pl, glo0);
                if (inter > 0.0f) q0 = iou_gt_half(inter, pw + w0 - inter);
                inter = fminf(ph, ghi1) - fmaxf(pl, glo1);
                if (inter > 0.0f) q1 = iou_gt_half(inter, pw + w1 - inter);
            }
            unsigned b0 = __ballot_sync(0xffffffffu, q0);
            unsigned b1 = __ballot_sync(0xffffffffu, q1);
            at &= ~(((u64)b1 << 32) | (u64)b0);
            at = (pos < 63) ? (at & (~0ull << (pos + 1))) : 0ull;
            if (lane == 0) keptLH[kt] = make_float2(pl, ph);
            kt++;
        }
        if (lane == 0) alive[t] = kept;
    };

    for (int g = 0; g < NPAIR; g++) {
        const int ta = 2 * g, tb = 2 * g + 1;
        u64 ata = alive[ta];
        u64 atb = alive[tb];
        if (ata == 0ull && atb == 0ull && dHi <= dLo)
            continue;   // dead round: no work, no writes, no barrier

        if (wid == 0) {
            const int T0 = kt;
            int stopAt = -1;
            do_tile(ta, ata, dLo, dHi);
            if (kt >= Kq) {
                stopAt = ta;
            } else {
                do_tile(tb, atb, dLo, kt);   // old delta + tile-a kept (contiguous)
                if (kt >= Kq) stopAt = tb;
            }
            if (lane == 0) {
                sDLo = T0;
                sDHi = kt;
                if (stopAt >= 0) { sStop = 1; sStopT = stopAt; }
            }
        } else {
            // background: apply round delta to strictly-later owned tiles
            if (wid > tb && myAlive && dHi > dLo) {
                unsigned killed = 0;
                #pragma unroll
                for (int r = 0; r < PER; r++) {
                    if (myAlive & (1u << r)) {
                        float lo = myLo[r], hi = myHi[r];
                        float wb = hi - lo;
                        for (int s = dLo; s < dHi; s++) {
                            float2 p = keptLH[s];
                            if (supp_test(lo, hi, wb, p)) { killed |= (1u << r); break; }
                        }
                    }
                }
                if (killed) {
                    myAlive &= ~killed;
                    atomicAnd(&alive[wid], ~((u64)killed << (lane * PER)));
                }
            }
        }
        __syncthreads();
        if (sStop) break;   // exactly K kept found; later tiles cannot matter
        dLo = sDLo;
        dHi = sDHi;
    }

    if (tid < NWORD && tid > sStopT) alive[tid] = 0ull;
    __syncthreads();

    // ---------- Phase 5: ranks + emit top-K with NEG padding ----------
    if (tid == 0) {
        int acc = 0;
        #pragma unroll
        for (int w = 0; w < NWORD; w++) { wp[w] = acc; acc += __popcll(alive[w]); }
        wp[NWORD] = acc;
    }
    __syncthreads();
    const int T = wp[NWORD];
    float* o = out + ((size_t)(b * 2 + c)) * Kq * 3;

    const u64 aw = alive[wid];
    #pragma unroll
    for (int r = 0; r < PER; r++) {
        int p = base + r;
        int bit = p & 63;
        u64 lowmask = (bit == 0) ? 0ull : ((1ull << bit) - 1ull);
        int  kr   = wp[p >> 6] + __popcll(aw & lowmask);
        bool kept = (aw >> bit) & 1ull;
        if (kept) {
            if (kr < Kq) {
                o[kr * 3 + 0] = myLo[r];
                o[kr * 3 + 1] = myHi[r];
                o[kr * 3 + 2] = key_to_score((unsigned)(myKey[r] >> 32));
            }
        } else {
            int nr = p - kr;
            if (T < Kq && nr < Kq - T) {
                int slot = T + nr;
                o[slot * 3 + 0] = myLo[r];
                o[slot * 3 + 1] = myHi[r];
                o[slot * 3 + 2] = NEGV;
            }
        }
    }
}

extern "C" void kernel_launch(void* const* d_in, const int* in_sizes, int n_in,
                              void* d_out, int out_size)
{
    const float* logit  = (const float*)d_in[0];   // [16,2048,3]
    const float* reg    = (const float*)d_in[1];   // [16,2048,6]
    const float* prop   = (const float*)d_in[2];   // [16,2048,2]
    const int*   ishape = (const int*)d_in[3];     // scalar
    float* out = (float*)d_out;                    // [16,2,100,3]

    cudaFuncSetAttribute(roiheads_kernel,
                         cudaFuncAttributeMaxDynamicSharedMemorySize, SMEM_DYN);
    roiheads_kernel<<<Bq * (Cq - 1), THREADS, SMEM_DYN>>>(logit, reg, prop, ishape, out);
}

// round 15
// speedup vs baseline: 4.2715x; 1.0562x over previous
#include <cuda_runtime.h>
#include <cstdint>

#define Bq 16
#define Nq 2048
#define Cq 3
#define Kq 100
#define THREADS 1024
#define PER (Nq / THREADS)   // 2 sorted positions per thread (contiguous, base=2*tid)
#define NWORD (Nq / 64)      // 32 bitmap words
#define NTILE (Nq / 64)      // 32 tiles of 64 sorted positions
#define KCAP 112
#define NEGV (-1e9f)
#define HSTRIDE 66           // u16 histogram row stride (bank-conflict-free scan)

// dynamic smem layout (bytes)
#define OFF_KEYSA 0
#define OFF_KEYSB 16384
#define OFF_LOHI  32768
#define OFF_HIST  49152                       // u16[256*66] = 33792
#define OFF_DTOT  (49152 + 33792)             // u32[256]
#define OFF_DBASE (OFF_DTOT + 1024)           // u32[256]
#define SMEM_DYN  (OFF_DBASE + 1024)          // 84992

typedef unsigned long long u64;
typedef unsigned u32;

__device__ __forceinline__ unsigned fkey_desc(float f) {
    unsigned u = __float_as_uint(f);
    u = (u & 0x80000000u) ? ~u : (u | 0x80000000u);
    return ~u;
}
__device__ __forceinline__ float key_to_score(unsigned k) {
    unsigned u = ~k;
    u = (u & 0x80000000u) ? (u & 0x7fffffffu) : ~u;
    return __uint_as_float(u);
}

// Exactly equivalent to (inter / fmaxf(uni,1e-8f)) > 0.5f for pairs that matter
// (alive boxes have width >= 10 so uni >= 10). Band fallback uses the literal
// reference expression; division rounding (<=0.5ulp) can't cross the band.
__device__ __forceinline__ bool iou_gt_half(float inter, float uni) {
    float h = 0.5f * uni;
    if (inter > h * 1.000002f) return true;
    if (inter < h * 0.999998f) return false;
    return inter / fmaxf(uni, 1e-8f) > 0.5f;
}

__device__ __forceinline__ bool supp_test(float lo, float hi, float wb, float2 p) {
    float inter = fminf(p.y, hi) - fmaxf(p.x, lo);
    float uni   = (p.y - p.x) + wb - inter;
    return (inter > 0.0f) && iou_gt_half(inter, uni);
}

// 32-bucket occupancy mask over [0, img]. Overlapping intervals ALWAYS have
// intersecting masks (any common point's bucket is in both ranges), so a
// disjoint mask proves inter <= 0 -> no suppression. Purely a filter; the
// actual test is unchanged.
__device__ __forceinline__ u32 bmask(float lo, float hi, float scale) {
    int b0 = (int)(lo * scale);
    int b1 = (int)(hi * scale);
    b0 = min(max(b0, 0), 31);
    b1 = min(max(b1, 0), 31);
    int d = b1 - b0;
    return (d >= 31) ? 0xffffffffu : (((2u << d) - 1u) << b0);
}

__global__ void __launch_bounds__(THREADS)
roiheads_kernel(const float* __restrict__ logit,   // [B,N,3]
                const float* __restrict__ reg,     // [B,N,6]
                const float* __restrict__ prop,    // [B,N,2]
                const int*   __restrict__ ishape,  // scalar
                float*       __restrict__ out)     // [B,2,K,3]
{
    extern __shared__ unsigned char dynsm[];
    u64*            keysA = (u64*)(dynsm + OFF_KEYSA);
    u64*            keysB = (u64*)(dynsm + OFF_KEYSB);
    float2*         lohi  = (float2*)(dynsm + OFF_LOHI);
    unsigned short* hist  = (unsigned short*)(dynsm + OFF_HIST);
    unsigned*       dtot  = (unsigned*)(dynsm + OFF_DTOT);
    unsigned*       dbase = (unsigned*)(dynsm + OFF_DBASE);

    __shared__ float2 keptLH[KCAP];
    __shared__ u32    keptMask[KCAP];
    __shared__ u64    alive[NWORD];
    __shared__ int    sDLo, sDHi;
    __shared__ int    sStop, sStopT;
    __shared__ int    wp[NWORD + 1];

    const int b    = blockIdx.x >> 1;
    const int c    = blockIdx.x & 1;
    const int cls  = c + 1;
    const int tid  = threadIdx.x;
    const int lane = tid & 31;
    const int wid  = tid >> 5;           // warp id == owned NMS tile
    const int base = tid * PER;

    int ib = ishape[0];
    float img = (ib > 0 && ib < (1 << 24)) ? (float)ib : __int_as_float(ib);
    const float scale = 32.0f / img;

    if (tid < NWORD) alive[tid] = 0ull;
    if (tid == 0) { sDLo = 0; sDHi = 0; sStop = 0; sStopT = NTILE - 1; }

    // ---------- Phase 1: softmax + decode + clip + mask -> keysA ----------
    {
        const float2* lgv = (const float2*)(logit + ((size_t)b * Nq + base) * Cq);
        float2 G0 = lgv[0], G1 = lgv[1], G2 = lgv[2];
        const float4  P   = *(const float4*)(prop + ((size_t)b * Nq + base) * 2);
        float lg[6] = {G0.x, G0.y, G1.x, G1.y, G2.x, G2.y};
        float pr[4] = {P.x, P.y, P.z, P.w};

        #pragma unroll
        for (int r = 0; r < PER; r++) {
            int j = base + r;
            float l0 = lg[r*3+0], l1 = lg[r*3+1], l2 = lg[r*3+2];
            float m  = fmaxf(l0, fmaxf(l1, l2));
            float e0 = expf(l0 - m), e1 = expf(l1 - m), e2 = expf(l2 - m);
            float s  = ((cls == 1) ? e1 : e2) / (e0 + e1 + e2);

            const float2 dd = *(const float2*)(reg + ((size_t)b * Nq + j) * (2 * Cq) + 2 * cls);
            float dx = dd.x;
            float dw = fminf(dd.y, 4.0f);

            float p0 = pr[r*2+0], p1 = pr[r*2+1];
            float w   = p1 - p0;
            float ctr = p0 + 0.5f * w;
            float pc  = dx * w + ctr;
            float pw  = expf(dw) * w;
            float lo  = fminf(fmaxf(pc - 0.5f * pw, 0.0f), img);
            float hi  = fminf(fmaxf(pc + 0.5f * pw, 0.0f), img);

            bool  valid = ((hi - lo) >= 10.0f) && (s >= 0.05f);
            float ms    = valid ? s : NEGV;

            lohi[j]  = make_float2(lo, hi);
            keysA[j] = ((u64)fkey_desc(ms) << 32) | (unsigned)j;
        }
    }
    __syncthreads();

    // ---------- Phase 2: stable LSD radix sort on score key (4 x 8-bit) ----------
    {
        u64* src = keysA;
        u64* dst = keysB;
        const unsigned lt = (1u << lane) - 1u;
        #pragma unroll
        for (int p = 0; p < 4; p++) {
            const int sh = 32 + p * 8;
            for (int i = tid; i < 256 * HSTRIDE; i += THREADS) hist[i] = 0;
            __syncthreads();

            u64 k0 = src[tid];
            u64 k1 = src[tid + 1024];
            unsigned d0 = (unsigned)(k0 >> sh) & 0xFFu;
            unsigned d1 = (unsigned)(k1 >> sh) & 0xFFu;
            unsigned m0 = __match_any_sync(0xffffffffu, d0);
            unsigned m1 = __match_any_sync(0xffffffffu, d1);
            if (__ffs(m0) - 1 == lane)
                hist[d0 * HSTRIDE + wid]      = (unsigned short)__popc(m0);
            if (__ffs(m1) - 1 == lane)
                hist[d1 * HSTRIDE + 32 + wid] = (unsigned short)__popc(m1);
            __syncthreads();

            if (tid < 256) {           // per-digit exclusive row prefix (in place)
                unsigned short* h = hist + tid * HSTRIDE;
                unsigned sum = 0;
                #pragma unroll
                for (int i = 0; i < 64; i++) {
                    unsigned t = h[i];
                    h[i] = (unsigned short)sum;
                    sum += t;
                }
                dtot[tid] = sum;
            }
            __syncthreads();

            if (tid < 32) {            // exclusive scan of 256 digit totals
                unsigned t8[8], run = 0;
                #pragma unroll
                for (int i = 0; i < 8; i++) t8[i] = dtot[tid * 8 + i];
                #pragma unroll
                for (int i = 0; i < 8; i++) { unsigned u = t8[i]; t8[i] = run; run += u; }
                unsigned inc = run;
                #pragma unroll
                for (int d = 1; d < 32; d <<= 1) {
                    unsigned x = __shfl_up_sync(0xffffffffu, inc, d);
                    if (lane >= d) inc += x;
                }
                unsigned excl = inc - run;
                #pragma unroll
                for (int i = 0; i < 8; i++) dbase[tid * 8 + i] = excl + t8[i];
            }
            __syncthreads();

            dst[dbase[d0] + hist[d0 * HSTRIDE + wid]      + __popc(m0 & lt)] = k0;
            dst[dbase[d1] + hist[d1 * HSTRIDE + 32 + wid] + __popc(m1 & lt)] = k1;
            __syncthreads();

            u64* tmp = src; src = dst; dst = tmp;   // after 4 passes: data in keysA
        }
    }

    // ---------- Phase 3: cache owned boxes + bucket masks; alive bitmap ----------
    u64 myKey[PER];
    float myLo[PER], myHi[PER];
    u32   myMask[PER];
    unsigned myAlive = 0;
    #pragma unroll
    for (int r = 0; r < PER; r++) {
        u64 key = keysA[base + r];
        myKey[r] = key;
        float2 lh = lohi[(int)(key & 0xffffffffu)];
        myLo[r] = lh.x;
        myHi[r] = lh.y;
        myMask[r] = bmask(lh.x, lh.y, scale);
        if (key_to_score((unsigned)(key >> 32)) > 0.5f * NEGV)
            myAlive |= (1u << r);
    }
    if (myAlive)
        atomicOr(&alive[wid], (u64)myAlive << (lane * PER));
    __syncthreads();

    // ---------- Phase 4: pipelined tile NMS, bucket-filtered suppression ----------
    int kt = 0;
    int dLo = 0, dHi = 0;

    for (int t = 0; t < NTILE; t++) {
        u64 at = alive[t];
        if (at == 0ull && dHi <= dLo) continue;   // dead round: no work, no writes

        if (wid == 0) {
            float2 a0 = lohi[(int)(keysA[t * 64 + lane     ] & 0xffffffffu)];
            float2 a1 = lohi[(int)(keysA[t * 64 + lane + 32] & 0xffffffffu)];
            const float glo0 = a0.x, ghi0 = a0.y, glo1 = a1.x, ghi1 = a1.y;
            const float w0 = ghi0 - glo0, w1 = ghi1 - glo1;
            const u32 gm0 = bmask(glo0, ghi0, scale);
            const u32 gm1 = bmask(glo1, ghi1, scale);
            const u32 gm01 = gm0 | gm1;
            const u64 pk0 = ((u64)__float_as_uint(ghi0) << 32) | __float_as_uint(glo0);
            const u64 pk1 = ((u64)__float_as_uint(ghi1) << 32) | __float_as_uint(glo1);

            // urgent: bucket-filtered suppression vs previous delta
            if (at != 0ull && dHi > dLo) {
                bool q0 = false, q1 = false;
                for (int s = dLo; s < dHi; s++) {
                    u32 km = keptMask[s];
                    if (km & gm01) {
                        float2 p = keptLH[s];
                        if (km & gm0) q0 |= supp_test(glo0, ghi0, w0, p);
                        if (km & gm1) q1 |= supp_test(glo1, ghi1, w1, p);
                    }
                }
                unsigned b0 = __ballot_sync(0xffffffffu, q0);
                unsigned b1 = __ballot_sync(0xffffffffu, q1);
                at &= ~(((u64)b1 << 32) | (u64)b0);
            }

            // greedy over the tile, capped at Kq kept total
            const int T0 = kt;
            u64 kept = 0;
            while (at && kt < Kq) {
                int pos = __ffsll((long long)at) - 1;
                kept |= (1ull << pos);
                u64 got = __shfl_sync(0xffffffffu, (pos & 32) ? pk1 : pk0, pos & 31);
                float pl = __uint_as_float((unsigned)(got & 0xffffffffu));
                float ph = __uint_as_float((unsigned)(got >> 32));
                float pw = ph - pl;
                bool q0 = false, q1 = false;
                {
                    float inter = fminf(ph, ghi0) - fmaxf(pl, glo0);
                    if (inter > 0.0f) q0 = iou_gt_half(inter, pw + w0 - inter);
                    inter = fminf(ph, ghi1) - fmaxf(pl, glo1);
                    if (inter > 0.0f) q1 = iou_gt_half(inter, pw + w1 - inter);
                }
                unsigned b0 = __ballot_sync(0xffffffffu, q0);
                unsigned b1 = __ballot_sync(0xffffffffu, q1);
                at &= ~(((u64)b1 << 32) | (u64)b0);
                at = (pos < 63) ? (at & (~0ull << (pos + 1))) : 0ull;
                if (lane == 0) {
                    keptLH[kt]   = make_float2(pl, ph);
                    keptMask[kt] = bmask(pl, ph, scale);
                }
                kt++;
            }
            if (lane == 0) {
                alive[t] = kept;
                sDLo = T0;
                sDHi = kt;
                if (kt >= Kq) { sStop = 1; sStopT = t; }
            }
        } else {
            // background: bucket-filtered suppression vs current delta
            if (wid > t && myAlive && dHi > dLo) {
                unsigned killed = 0;
                #pragma unroll
                for (int r = 0; r < PER; r++) {
                    if (myAlive & (1u << r)) {
                        float lo = myLo[r], hi = myHi[r];
                        float wb = hi - lo;
                        u32 mm = myMask[r];
                        for (int s = dLo; s < dHi; s++) {
                            if (keptMask[s] & mm) {
                                if (supp_test(lo, hi, wb, keptLH[s])) {
                                    killed |= (1u << r);
                                    break;
                                }
                            }
                        }
                    }
                }
                if (killed) {
                    myAlive &= ~killed;
                    atomicAnd(&alive[wid], ~((u64)killed << (lane * PER)));
                }
            }
        }
        __syncthreads();
        if (sStop) break;
        dLo = sDLo;
        dHi = sDHi;
    }

    if (tid < NWORD && tid > sStopT) alive[tid] = 0ull;
    __syncthreads();

    // ---------- Phase 5: ranks + emit top-K with NEG padding ----------
    if (tid == 0) {
        int acc = 0;
        #pragma unroll
        for (int w = 0; w < NWORD; w++) { wp[w] = acc; acc += __popcll(alive[w]); }
        wp[NWORD] = acc;
    }
    __syncthreads();
    const int T = wp[NWORD];
    float* o = out + ((size_t)(b * 2 + c)) * Kq * 3;

    const u64 aw = alive[wid];
    #pragma unroll
    for (int r = 0; r < PER; r++) {
        int p = base + r;
        int bit = p & 63;
        u64 lowmask = (bit == 0) ? 0ull : ((1ull << bit) - 1ull);
        int  kr   = wp[p >> 6] + __popcll(aw & lowmask);
        bool kept = (aw >> bit) & 1ull;
        if (kept) {
            if (kr < Kq) {
                o[kr * 3 + 0] = myLo[r];
                o[kr * 3 + 1] = myHi[r];
                o[kr * 3 + 2] = key_to_score((unsigned)(myKey[r] >> 32));
            }
        } else {
            int nr = p - kr;
            if (T < Kq && nr < Kq - T) {
                int slot = T + nr;
                o[slot * 3 + 0] = myLo[r];
                o[slot * 3 + 1] = myHi[r];
                o[slot * 3 + 2] = NEGV;
            }
        }
    }
}

extern "C" void kernel_launch(void* const* d_in, const int* in_sizes, int n_in,
                              void* d_out, int out_size)
{
    const float* logit  = (const float*)d_in[0];   // [16,2048,3]
    const float* reg    = (const float*)d_in[1];   // [16,2048,6]
    const float* prop   = (const float*)d_in[2];   // [16,2048,2]
    const int*   ishape = (const int*)d_in[3];     // scalar
    float* out = (float*)d_out;                    // [16,2,100,3]

    cudaFuncSetAttribute(roiheads_kernel,
                         cudaFuncAttributeMaxDynamicSharedMemorySize, SMEM_DYN);
    roiheads_kernel<<<Bq * (Cq - 1), THREADS, SMEM_DYN>>>(logit, reg, prop, ishape, out);
}

// round 16
// speedup vs baseline: 5.0465x; 1.1814x over previous
#include <cuda_runtime.h>
#include <cstdint>

#define Bq 16
#define Nq 2048
#define Cq 3
#define Kq 100
#define THREADS 1024
#define PER 2                // owned sorted positions per thread (strided in tile)
#define NWORD (Nq / 64)      // 32 bitmap words
#define NTILE (Nq / 64)      // 32 tiles; warp w owns tile w
#define KCAP 112
#define NEGV (-1e9f)
#define HSTRIDE 66           // u16 histogram row stride (bank-conflict-free scan)

// dynamic smem layout (bytes)
#define OFF_KEYSA 0
#define OFF_KEYSB 16384
#define OFF_LOHI  32768
#define OFF_HIST  49152                       // u16[256*66] = 33792
#define OFF_DTOT  (49152 + 33792)             // u32[256]
#define OFF_DBASE (OFF_DTOT + 1024)           // u32[256]
#define SMEM_DYN  (OFF_DBASE + 1024)          // 84992

typedef unsigned long long u64;

__device__ __forceinline__ unsigned fkey_desc(float f) {
    unsigned u = __float_as_uint(f);
    u = (u & 0x80000000u) ? ~u : (u | 0x80000000u);
    return ~u;
}
__device__ __forceinline__ float key_to_score(unsigned k) {
    unsigned u = ~k;
    u = (u & 0x80000000u) ? (u & 0x7fffffffu) : ~u;
    return __uint_as_float(u);
}

// Exactly equivalent to (inter / fmaxf(uni,1e-8f)) > 0.5f for pairs that matter
// (alive boxes have width >= 10 so uni >= 10). Band fallback uses the literal
// reference expression; division rounding (<=0.5ulp) can't cross the band.
__device__ __forceinline__ bool iou_gt_half(float inter, float uni) {
    float h = 0.5f * uni;
    if (inter > h * 1.000002f) return true;
    if (inter < h * 0.999998f) return false;
    return inter / fmaxf(uni, 1e-8f) > 0.5f;
}

__device__ __forceinline__ bool supp_test(float lo, float hi, float wb, float2 p) {
    float inter = fminf(p.y, hi) - fmaxf(p.x, lo);
    float uni   = (p.y - p.x) + wb - inter;
    return (inter > 0.0f) && iou_gt_half(inter, uni);
}

__global__ void __launch_bounds__(THREADS)
roiheads_kernel(const float* __restrict__ logit,   // [B,N,3]
                const float* __restrict__ reg,     // [B,N,6]
                const float* __restrict__ prop,    // [B,N,2]
                const int*   __restrict__ ishape,  // scalar
                float*       __restrict__ out)     // [B,2,K,3]
{
    extern __shared__ unsigned char dynsm[];
    u64*            keysA = (u64*)(dynsm + OFF_KEYSA);
    u64*            keysB = (u64*)(dynsm + OFF_KEYSB);
    float2*         lohi  = (float2*)(dynsm + OFF_LOHI);
    unsigned short* hist  = (unsigned short*)(dynsm + OFF_HIST);
    unsigned*       dtot  = (unsigned*)(dynsm + OFF_DTOT);
    unsigned*       dbase = (unsigned*)(dynsm + OFF_DBASE);

    __shared__ float2 keptLH[KCAP];
    __shared__ u64    alive[NWORD];
    __shared__ int    sDLo, sDHi;
    __shared__ int    sStop, sStopT;
    __shared__ int    wp[NWORD + 1];

    const int b    = blockIdx.x >> 1;
    const int c    = blockIdx.x & 1;
    const int cls  = c + 1;
    const int tid  = threadIdx.x;
    const int lane = tid & 31;
    const int wid  = tid >> 5;           // warp id == owned NMS tile
    const int cbase = tid * 2;           // phase-1 contiguous partition only

    int ib = ishape[0];
    float img = (ib > 0 && ib < (1 << 24)) ? (float)ib : __int_as_float(ib);

    if (tid < NWORD) alive[tid] = 0ull;
    if (tid == 0) { sDLo = 0; sDHi = 0; sStop = 0; sStopT = NTILE - 1; }

    // ---------- Phase 1: softmax + decode + clip + mask -> keysA ----------
    {
        const float2* lgv = (const float2*)(logit + ((size_t)b * Nq + cbase) * Cq);
        float2 G0 = lgv[0], G1 = lgv[1], G2 = lgv[2];
        const float4  P   = *(const float4*)(prop + ((size_t)b * Nq + cbase) * 2);
        float lg[6] = {G0.x, G0.y, G1.x, G1.y, G2.x, G2.y};
        float pr[4] = {P.x, P.y, P.z, P.w};

        #pragma unroll
        for (int r = 0; r < 2; r++) {
            int j = cbase + r;
            float l0 = lg[r*3+0], l1 = lg[r*3+1], l2 = lg[r*3+2];
            float m  = fmaxf(l0, fmaxf(l1, l2));
            float e0 = expf(l0 - m), e1 = expf(l1 - m), e2 = expf(l2 - m);
            float s  = ((cls == 1) ? e1 : e2) / (e0 + e1 + e2);

            const float2 dd = *(const float2*)(reg + ((size_t)b * Nq + j) * (2 * Cq) + 2 * cls);
            float dx = dd.x;
            float dw = fminf(dd.y, 4.0f);

            float p0 = pr[r*2+0], p1 = pr[r*2+1];
            float w   = p1 - p0;
            float ctr = p0 + 0.5f * w;
            float pc  = dx * w + ctr;
            float pw  = expf(dw) * w;
            float lo  = fminf(fmaxf(pc - 0.5f * pw, 0.0f), img);
            float hi  = fminf(fmaxf(pc + 0.5f * pw, 0.0f), img);

            bool  valid = ((hi - lo) >= 10.0f) && (s >= 0.05f);
            float ms    = valid ? s : NEGV;

            lohi[j]  = make_float2(lo, hi);
            keysA[j] = ((u64)fkey_desc(ms) << 32) | (unsigned)j;
        }
    }
    __syncthreads();

    // ---------- Phase 2: stable LSD radix sort on score key (4 x 8-bit) ----------
    {
        u64* src = keysA;
        u64* dst = keysB;
        const unsigned lt = (1u << lane) - 1u;
        #pragma unroll
        for (int p = 0; p < 4; p++) {
            const int sh = 32 + p * 8;
            for (int i = tid; i < 256 * HSTRIDE; i += THREADS) hist[i] = 0;
            __syncthreads();

            u64 k0 = src[tid];
            u64 k1 = src[tid + 1024];
            unsigned d0 = (unsigned)(k0 >> sh) & 0xFFu;
            unsigned d1 = (unsigned)(k1 >> sh) & 0xFFu;
            unsigned m0 = __match_any_sync(0xffffffffu, d0);
            unsigned m1 = __match_any_sync(0xffffffffu, d1);
            if (__ffs(m0) - 1 == lane)
                hist[d0 * HSTRIDE + wid]      = (unsigned short)__popc(m0);
            if (__ffs(m1) - 1 == lane)
                hist[d1 * HSTRIDE + 32 + wid] = (unsigned short)__popc(m1);
            __syncthreads();

            if (tid < 256) {           // per-digit exclusive row prefix (in place)
                unsigned short* h = hist + tid * HSTRIDE;
                unsigned sum = 0;
                #pragma unroll
                for (int i = 0; i < 64; i++) {
                    unsigned t = h[i];
                    h[i] = (unsigned short)sum;
                    sum += t;
                }
                dtot[tid] = sum;
            }
            __syncthreads();

            if (tid < 32) {            // exclusive scan of 256 digit totals
                unsigned t8[8], run = 0;
                #pragma unroll
                for (int i = 0; i < 8; i++) t8[i] = dtot[tid * 8 + i];
                #pragma unroll
                for (int i = 0; i < 8; i++) { unsigned u = t8[i]; t8[i] = run; run += u; }
                unsigned inc = run;
                #pragma unroll
                for (int d = 1; d < 32; d <<= 1) {
                    unsigned x = __shfl_up_sync(0xffffffffu, inc, d);
                    if (lane >= d) inc += x;
                }
                unsigned excl = inc - run;
                #pragma unroll
                for (int i = 0; i < 8; i++) dbase[tid * 8 + i] = excl + t8[i];
            }
            __syncthreads();

            dst[dbase[d0] + hist[d0 * HSTRIDE + wid]      + __popc(m0 & lt)] = k0;
            dst[dbase[d1] + hist[d1 * HSTRIDE + 32 + wid] + __popc(m1 & lt)] = k1;
            __syncthreads();

            u64* tmp = src; src = dst; dst = tmp;   // after 4 passes: data in keysA
        }
    }

    // ---------- Phase 3: cache owned boxes (strided in tile); alive bitmap ----------
    // Thread owns sorted positions wid*64 + lane + 32*r  (r = 0,1):
    // warp-local layout matches the greedy's {L, L+32} ballot mapping, and
    // tile bit index == lane + 32*r.
    u64 myKey[2];
    float myLo[2], myHi[2];
    unsigned myAlive = 0;
    #pragma unroll
    for (int r = 0; r < 2; r++) {
        int pos = wid * 64 + lane + 32 * r;
        u64 key = keysA[pos];
        myKey[r] = key;
        float2 lh = lohi[(int)(key & 0xffffffffu)];
        myLo[r] = lh.x;
        myHi[r] = lh.y;
        if (key_to_score((unsigned)(key >> 32)) > 0.5f * NEGV)
            myAlive |= (1u << r);
    }
    if (myAlive)
        atomicOr(&alive[wid], ((u64)(myAlive & 1u) << lane)
                            | ((u64)((myAlive >> 1) & 1u) << (lane + 32)));
    __syncthreads();

    // ---------- Phase 4: rotating-greedy tile NMS with dead-round skipping ----------
    int kt = 0;
    int dLo = 0, dHi = 0;

    for (int t = 0; t < NTILE; t++) {
        u64 at = alive[t];
        if (at == 0ull && dHi <= dLo) continue;   // dead round: no work, no writes

        if (wid == t) {
            // greedy warp: tile boxes already in registers, zero LDS for boxes
            const float glo0 = myLo[0], ghi0 = myHi[0];
            const float glo1 = myLo[1], ghi1 = myHi[1];
            const float w0 = ghi0 - glo0, w1 = ghi1 - glo1;
            const u64 pk0 = ((u64)__float_as_uint(ghi0) << 32) | __float_as_uint(glo0);
            const u64 pk1 = ((u64)__float_as_uint(ghi1) << 32) | __float_as_uint(glo1);

            // urgent: apply previous round's kept delta (register boxes)
            if (at != 0ull && dHi > dLo) {
                bool q0 = false, q1 = false;
                for (int s = dLo; s < dHi; s++) {
                    float2 p = keptLH[s];
                    q0 |= supp_test(glo0, ghi0, w0, p);
                    q1 |= supp_test(glo1, ghi1, w1, p);
                }
                unsigned b0 = __ballot_sync(0xffffffffu, q0);
                unsigned b1 = __ballot_sync(0xffffffffu, q1);
                at &= ~(((u64)b1 << 32) | (u64)b0);
            }

            // greedy over the tile, capped at Kq kept total
            const int T0 = kt;
            u64 kept = 0;
            while (at && kt < Kq) {
                int pos = __ffsll((long long)at) - 1;
                kept |= (1ull << pos);
                u64 got = __shfl_sync(0xffffffffu, (pos & 32) ? pk1 : pk0, pos & 31);
                float pl = __uint_as_float((unsigned)(got & 0xffffffffu));
                float ph = __uint_as_float((unsigned)(got >> 32));
                float pw = ph - pl;
                bool q0 = false, q1 = false;
                {
                    float inter = fminf(ph, ghi0) - fmaxf(pl, glo0);
                    if (inter > 0.0f) q0 = iou_gt_half(inter, pw + w0 - inter);
                    inter = fminf(ph, ghi1) - fmaxf(pl, glo1);
                    if (inter > 0.0f) q1 = iou_gt_half(inter, pw + w1 - inter);
                }
                unsigned b0 = __ballot_sync(0xffffffffu, q0);
                unsigned b1 = __ballot_sync(0xffffffffu, q1);
                at &= ~(((u64)b1 << 32) | (u64)b0);
                at = (pos < 63) ? (at & (~0ull << (pos + 1))) : 0ull;
                if (lane == 0) keptLH[kt] = make_float2(pl, ph);
                kt++;
            }
            if (lane == 0) {
                alive[t] = kept;
                sDLo = T0;
                sDHi = kt;
                if (kt >= Kq) { sStop = 1; sStopT = t; }
            }
        } else if (wid > t && myAlive && dHi > dLo) {
            // background: apply current delta to my (still-pending) tile boxes
            unsigned killed = 0;
            #pragma unroll
            for (int r = 0; r < 2; r++) {
                if (myAlive & (1u << r)) {
                    float lo = myLo[r], hi = myHi[r];
                    float wb = hi - lo;
                    for (int s = dLo; s < dHi; s++) {
                        float2 p = keptLH[s];
                        if (supp_test(lo, hi, wb, p)) { killed |= (1u << r); break; }
                    }
                }
            }
            if (killed) {
                myAlive &= ~killed;
                atomicAnd(&alive[wid], ~(((u64)(killed & 1u) << lane)
                                       | ((u64)((killed >> 1) & 1u) << (lane + 32))));
            }
        }
        __syncthreads();
        if (sStop) break;
        dLo = sDLo;
        dHi = sDHi;
    }

    if (tid < NWORD && tid > sStopT) alive[tid] = 0ull;
    __syncthreads();

    // ---------- Phase 5: ranks + emit top-K with NEG padding ----------
    if (tid == 0) {
        int acc = 0;
        #pragma unroll
        for (int w = 0; w < NWORD; w++) { wp[w] = acc; acc += __popcll(alive[w]); }
        wp[NWORD] = acc;
    }
    __syncthreads();
    const int T = wp[NWORD];
    float* o = out + ((size_t)(b * 2 + c)) * Kq * 3;

    const u64 aw = alive[wid];
    #pragma unroll
    for (int r = 0; r < 2; r++) {
        int bit = lane + 32 * r;
        int p   = wid * 64 + bit;
        u64 lowmask = (bit == 0) ? 0ull : ((1ull << bit) - 1ull);
        int  kr   = wp[wid] + __popcll(aw & lowmask);
        bool kept = (aw >> bit) & 1ull;
        if (kept) {
            if (kr < Kq) {
                o[kr * 3 + 0] = myLo[r];
                o[kr * 3 + 1] = myHi[r];
                o[kr * 3 + 2] = key_to_score((unsigned)(myKey[r] >> 32));
            }
        } else {
            int nr = p - kr;
            if (T < Kq && nr < Kq - T) {
                int slot = T + nr;
                o[slot * 3 + 0] = myLo[r];
                o[slot * 3 + 1] = myHi[r];
                o[slot * 3 + 2] = NEGV;
            }
        }
    }
}

extern "C" void kernel_launch(void* const* d_in, const int* in_sizes, int n_in,
                              void* d_out, int out_size)
{
    const float* logit  = (const float*)d_in[0];   // [16,2048,3]
    const float* reg    = (const float*)d_in[1];   // [16,2048,6]
    const float* prop   = (const float*)d_in[2];   // [16,2048,2]
    const int*   ishape = (const int*)d_in[3];     // scalar
    float* out = (float*)d_out;                    // [16,2,100,3]

    cudaFuncSetAttribute(roiheads_kernel,
                         cudaFuncAttributeMaxDynamicSharedMemorySize, SMEM_DYN);
    roiheads_kernel<<<Bq * (Cq - 1), THREADS, SMEM_DYN>>>(logit, reg, prop, ishape, out);
}